// round 4
// baseline (speedup 1.0000x reference)
#include <cuda_runtime.h>
#include <cuda_bf16.h>
#include <math.h>

#define Bb 32
#define Ss 32
#define Nn 128
#define Uu 64
#define Ee 2
#define Ll 2
#define NSTEP 3
#define NC 5

// Scratch (allocation-free): h state and typed messages
__device__ float g_h[Bb * Nn * Uu];          // 1 MB
__device__ float g_M[Bb * Ee * Nn * Uu];     // 2 MB

// ---------------------------------------------------------------------------
// Gather: h0[b] = input_seq[b, clip(seq_lengths[b]-1, 0, S-1)]  (8192 floats)
// ---------------------------------------------------------------------------
__global__ void gather_kernel(const float* __restrict__ input_seq,
                              const int* __restrict__ seq_lengths) {
    int b = blockIdx.x;
    int idx = seq_lengths[b] - 1;
    if (idx < 0) idx = 0;
    if (idx > Ss - 1) idx = Ss - 1;
    const float* src = input_seq + ((size_t)b * Ss + idx) * (Nn * Uu);
    float* dst = g_h + (size_t)b * (Nn * Uu);
    for (int i = threadIdx.x * 4; i < Nn * Uu; i += blockDim.x * 4) {
        *(float4*)&dst[i] = *(const float4*)&src[i];
    }
}

// ---------------------------------------------------------------------------
// msgmm: M[b,e,tile*32 .. +31, :] = A[b,e,rows,:] @ h[b]   ([32,128]@[128,64])
// grid(4, E, B), 256 threads. Register-tiled 2x4 per thread.
// ---------------------------------------------------------------------------
__global__ void msgmm_kernel(const float* __restrict__ A) {
    int tile = blockIdx.x;   // 0..3  (32 rows each)
    int e    = blockIdx.y;
    int b    = blockIdx.z;

    __shared__ float sh[Nn][Uu];   // full h for this batch (32 KB)
    __shared__ float sA[32][32];   // A chunk (4 KB)

    int tid = threadIdx.x;
    int tx = tid & 15;             // col group (4 cols)
    int ty = tid >> 4;             // row group (2 rows)

    const float* hb = g_h + (size_t)b * Nn * Uu;
    for (int i = tid * 4; i < Nn * Uu; i += 1024)
        *(float4*)&sh[0][i] = *(const float4*)&hb[i];

    const float* Ab = A + (((size_t)b * Ee + e) * Nn + tile * 32) * Nn;

    float acc[2][4] = {};

    for (int kk = 0; kk < Nn; kk += 32) {
        __syncthreads();   // sh ready (first iter) / previous chunk consumed
        for (int i = tid; i < 32 * 32; i += 256) {
            int r = i >> 5, c = i & 31;
            sA[r][c] = Ab[(size_t)r * Nn + kk + c];
        }
        __syncthreads();
        #pragma unroll
        for (int k = 0; k < 32; k++) {
            float a0 = sA[ty * 2][k];
            float a1 = sA[ty * 2 + 1][k];
            float4 bv = *(const float4*)&sh[kk + k][tx * 4];
            acc[0][0] += a0 * bv.x; acc[0][1] += a0 * bv.y;
            acc[0][2] += a0 * bv.z; acc[0][3] += a0 * bv.w;
            acc[1][0] += a1 * bv.x; acc[1][1] += a1 * bv.y;
            acc[1][2] += a1 * bv.z; acc[1][3] += a1 * bv.w;
        }
    }

    float* Mout = g_M + (((size_t)b * Ee + e) * Nn + tile * 32) * Uu;
    #pragma unroll
    for (int rr = 0; rr < 2; rr++) {
        int row = ty * 2 + rr;
        float4 v = make_float4(acc[rr][0], acc[rr][1], acc[rr][2], acc[rr][3]);
        *(float4*)&Mout[(size_t)row * Uu + tx * 4] = v;
    }
}

// ---------------------------------------------------------------------------
// rowupdate: fully fused per-row GRU-style gate update.
//   a = M0@W0 + M1@W1 + b_msg
//   z = sig(a@Wg0 + h@Ug0 + bg0); r = sig(a@Wg1 + h@Ug1 + bg1)
//   c = tanh(a@Wg2 + (r*h)@Ug2 + bg2); h = (1-z)h + z c
// grid(8, B): 16 rows per block, 256 threads. Thread owns (row, 4 cols).
// ---------------------------------------------------------------------------
__global__ void rowupdate_kernel(const float* __restrict__ W_msg,
                                 const float* __restrict__ b_msg,
                                 const float* __restrict__ Wg,
                                 const float* __restrict__ Ug,
                                 const float* __restrict__ bg,
                                 int l) {
    int tile = blockIdx.x;   // 0..7
    int b    = blockIdx.y;

    __shared__ float sh[16][64];
    __shared__ float sM0[16][64];   // reused as rh buffer after 'a' phase
    __shared__ float sM1[16][64];
    __shared__ float sa[16][64];
    __shared__ float sW[64][64];

    int tid = threadIdx.x;
    int row = tid >> 4;      // 0..15
    int cg  = tid & 15;
    int col = cg * 4;
    int r0  = tile * 16;

    const float* hb = g_h + ((size_t)b * Nn + r0) * Uu;
    const float* M0 = g_M + (((size_t)b * Ee + 0) * Nn + r0) * Uu;
    const float* M1 = g_M + (((size_t)b * Ee + 1) * Nn + r0) * Uu;

    {
        int i = tid * 4;  // covers 0..1020, exactly all 1024 floats
        *(float4*)&sh[0][i]  = *(const float4*)&hb[i];
        *(float4*)&sM0[0][i] = *(const float4*)&M0[i];
        *(float4*)&sM1[0][i] = *(const float4*)&M1[i];
    }

    // stage one 64x64 weight matrix into sW (syncs protect prior readers
    // of sW and make freshly written tiles visible)
    auto loadW = [&](const float* src) {
        __syncthreads();
        for (int i = tid * 4; i < 4096; i += 1024)
            *(float4*)&sW[0][i] = *(const float4*)&src[i];
        __syncthreads();
    };

    auto gemm = [&](float* accv, const float (*X)[64]) {
        #pragma unroll 4
        for (int k = 0; k < 64; k++) {
            float x = X[row][k];
            float4 w = *(const float4*)&sW[k][col];
            accv[0] += x * w.x; accv[1] += x * w.y;
            accv[2] += x * w.z; accv[3] += x * w.w;
        }
    };

    // --- a = M0@W0 + M1@W1 + b_msg ---
    float acc[4] = {0.f, 0.f, 0.f, 0.f};
    loadW(W_msg + ((size_t)l * Ee + 0) * Uu * Uu);
    float4 h4 = *(const float4*)&sh[row][col];   // tiles visible after loadW sync
    gemm(acc, sM0);
    loadW(W_msg + ((size_t)l * Ee + 1) * Uu * Uu);
    gemm(acc, sM1);
    {
        float4 bm = *(const float4*)&b_msg[l * Uu + col];
        acc[0] += bm.x; acc[1] += bm.y; acc[2] += bm.z; acc[3] += bm.w;
        *(float4*)&sa[row][col] = make_float4(acc[0], acc[1], acc[2], acc[3]);
    }

    // --- z = sigmoid(a@Wg0 + h@Ug0 + bg0) ---
    float accz[4];
    {
        float4 bb = *(const float4*)&bg[((size_t)l * 3 + 0) * Uu + col];
        accz[0] = bb.x; accz[1] = bb.y; accz[2] = bb.z; accz[3] = bb.w;
    }
    loadW(Ug + ((size_t)l * 3 + 0) * Uu * Uu);   // sync also publishes sa
    gemm(accz, sh);
    loadW(Wg + ((size_t)l * 3 + 0) * Uu * Uu);
    gemm(accz, sa);
    float z[4];
    #pragma unroll
    for (int j = 0; j < 4; j++) z[j] = 1.0f / (1.0f + expf(-accz[j]));

    // --- r = sigmoid(a@Wg1 + h@Ug1 + bg1); rh = r*h (into sM0) ---
    float accr[4];
    {
        float4 bb = *(const float4*)&bg[((size_t)l * 3 + 1) * Uu + col];
        accr[0] = bb.x; accr[1] = bb.y; accr[2] = bb.z; accr[3] = bb.w;
    }
    loadW(Ug + ((size_t)l * 3 + 1) * Uu * Uu);
    gemm(accr, sh);
    loadW(Wg + ((size_t)l * 3 + 1) * Uu * Uu);
    gemm(accr, sa);
    {
        float r_[4];
        #pragma unroll
        for (int j = 0; j < 4; j++) r_[j] = 1.0f / (1.0f + expf(-accr[j]));
        float4 rh = make_float4(r_[0] * h4.x, r_[1] * h4.y, r_[2] * h4.z, r_[3] * h4.w);
        *(float4*)&sM0[row][col] = rh;
    }

    // --- c = tanh(a@Wg2 + rh@Ug2 + bg2) ---
    float accc[4];
    {
        float4 bb = *(const float4*)&bg[((size_t)l * 3 + 2) * Uu + col];
        accc[0] = bb.x; accc[1] = bb.y; accc[2] = bb.z; accc[3] = bb.w;
    }
    loadW(Ug + ((size_t)l * 3 + 2) * Uu * Uu);   // sync publishes rh in sM0
    gemm(accc, sM0);
    loadW(Wg + ((size_t)l * 3 + 2) * Uu * Uu);
    gemm(accc, sa);

    // --- h_new = (1-z)*h + z*c ---
    float hn[4];
    hn[0] = (1.0f - z[0]) * h4.x + z[0] * tanhf(accc[0]);
    hn[1] = (1.0f - z[1]) * h4.y + z[1] * tanhf(accc[1]);
    hn[2] = (1.0f - z[2]) * h4.z + z[2] * tanhf(accc[2]);
    hn[3] = (1.0f - z[3]) * h4.w + z[3] * tanhf(accc[3]);

    float* hout = g_h + ((size_t)b * Nn + r0 + row) * Uu + col;
    *(float4*)hout = make_float4(hn[0], hn[1], hn[2], hn[3]);
}

// ---------------------------------------------------------------------------
// final: logits[b,n,:] = relu(h[b,n,:]) @ fc_w + fc_b; out[b,:] = max over n
// grid(B), 128 threads (one per n).
// ---------------------------------------------------------------------------
__global__ void final_kernel(const float* __restrict__ fc_w,
                             const float* __restrict__ fc_b,
                             float* __restrict__ out) {
    int b = blockIdx.x;
    int n = threadIdx.x;   // 0..127

    __shared__ float sw[Uu * NC];
    __shared__ float slog[Nn][NC];

    for (int i = n; i < Uu * NC; i += 128) sw[i] = fc_w[i];
    __syncthreads();

    const float* hrow = g_h + ((size_t)b * Nn + n) * Uu;
    float acc[NC];
    #pragma unroll
    for (int c = 0; c < NC; c++) acc[c] = fc_b[c];
    for (int u = 0; u < Uu; u++) {
        float v = hrow[u];
        v = v > 0.f ? v : 0.f;
        #pragma unroll
        for (int c = 0; c < NC; c++) acc[c] += v * sw[u * NC + c];
    }
    #pragma unroll
    for (int c = 0; c < NC; c++) slog[n][c] = acc[c];
    __syncthreads();

    for (int s = 64; s > 0; s >>= 1) {
        if (n < s) {
            #pragma unroll
            for (int c = 0; c < NC; c++)
                slog[n][c] = fmaxf(slog[n][c], slog[n + s][c]);
        }
        __syncthreads();
    }
    if (n < NC) out[b * NC + n] = slog[0][n];
}

// ---------------------------------------------------------------------------
// Launch
// ---------------------------------------------------------------------------
extern "C" void kernel_launch(void* const* d_in, const int* in_sizes, int n_in,
                              void* d_out, int out_size) {
    const float* input_seq   = (const float*)d_in[0];  // (B,S,N*U)
    const int*   seq_lengths = (const int*)d_in[1];    // (B,)
    const float* Adj         = (const float*)d_in[2];  // (B,E,N,N)
    const float* W_msg       = (const float*)d_in[3];  // (L,E,U,U)
    const float* b_msg       = (const float*)d_in[4];  // (L,U)
    const float* Wg          = (const float*)d_in[5];  // (L,3,U,U)
    const float* Ug          = (const float*)d_in[6];  // (L,3,U,U)
    const float* bg          = (const float*)d_in[7];  // (L,3,U)
    const float* fc_w        = (const float*)d_in[8];  // (U,NC)
    const float* fc_b        = (const float*)d_in[9];  // (NC,)
    float* out = (float*)d_out;

    gather_kernel<<<Bb, 256>>>(input_seq, seq_lengths);

    for (int l = 0; l < Ll; l++) {
        for (int s = 0; s < NSTEP; s++) {
            msgmm_kernel<<<dim3(4, Ee, Bb), 256>>>(Adj);
            rowupdate_kernel<<<dim3(8, Bb), 256>>>(W_msg, b_msg, Wg, Ug, bg, l);
        }
    }

    final_kernel<<<Bb, 128>>>(fc_w, fc_b, out);
}

// round 6
// speedup vs baseline: 1.0023x; 1.0023x over previous
#include <cuda_runtime.h>
#include <cuda_bf16.h>
#include <math.h>

#define Bb 32
#define Ss 32
#define Nn 128
#define Uu 64
#define Ee 2
#define Ll 2
#define NSTEP 3
#define NC 5

// Scratch (allocation-free): h state and typed messages
__device__ float g_h[Bb * Nn * Uu];          // 1 MB
__device__ float g_M[Bb * Ee * Nn * Uu];     // 2 MB

// ---------------------------------------------------------------------------
// Gather: h0[b] = input_seq[b, clip(seq_lengths[b]-1, 0, S-1)]  (8192 floats)
// ---------------------------------------------------------------------------
__global__ void gather_kernel(const float* __restrict__ input_seq,
                              const int* __restrict__ seq_lengths) {
    int b = blockIdx.x;
    int idx = seq_lengths[b] - 1;
    if (idx < 0) idx = 0;
    if (idx > Ss - 1) idx = Ss - 1;
    const float* src = input_seq + ((size_t)b * Ss + idx) * (Nn * Uu);
    float* dst = g_h + (size_t)b * (Nn * Uu);
    for (int i = threadIdx.x * 4; i < Nn * Uu; i += blockDim.x * 4) {
        *(float4*)&dst[i] = *(const float4*)&src[i];
    }
}

// ---------------------------------------------------------------------------
// msgmm: M[b,e,tile*32 .. +31, :] = A[b,e,rows,:] @ h[b]   ([32,128]@[128,64])
// grid(4, E, B), 256 threads. Register-tiled 2x4 per thread.
// ---------------------------------------------------------------------------
__global__ void msgmm_kernel(const float* __restrict__ A) {
    int tile = blockIdx.x;   // 0..3  (32 rows each)
    int e    = blockIdx.y;
    int b    = blockIdx.z;

    __shared__ float sh[Nn][Uu];   // full h for this batch (32 KB)
    __shared__ float sA[32][32];   // A chunk (4 KB)

    int tid = threadIdx.x;
    int tx = tid & 15;             // col group (4 cols)
    int ty = tid >> 4;             // row group (2 rows)

    const float* hb = g_h + (size_t)b * Nn * Uu;
    for (int i = tid * 4; i < Nn * Uu; i += 1024)
        *(float4*)&sh[0][i] = *(const float4*)&hb[i];

    const float* Ab = A + (((size_t)b * Ee + e) * Nn + tile * 32) * Nn;

    float acc[2][4] = {};

    for (int kk = 0; kk < Nn; kk += 32) {
        __syncthreads();   // sh ready (first iter) / previous chunk consumed
        for (int i = tid; i < 32 * 32; i += 256) {
            int r = i >> 5, c = i & 31;
            sA[r][c] = Ab[(size_t)r * Nn + kk + c];
        }
        __syncthreads();
        #pragma unroll
        for (int k = 0; k < 32; k++) {
            float a0 = sA[ty * 2][k];
            float a1 = sA[ty * 2 + 1][k];
            float4 bv = *(const float4*)&sh[kk + k][tx * 4];
            acc[0][0] += a0 * bv.x; acc[0][1] += a0 * bv.y;
            acc[0][2] += a0 * bv.z; acc[0][3] += a0 * bv.w;
            acc[1][0] += a1 * bv.x; acc[1][1] += a1 * bv.y;
            acc[1][2] += a1 * bv.z; acc[1][3] += a1 * bv.w;
        }
    }

    float* Mout = g_M + (((size_t)b * Ee + e) * Nn + tile * 32) * Uu;
    #pragma unroll
    for (int rr = 0; rr < 2; rr++) {
        int row = ty * 2 + rr;
        float4 v = make_float4(acc[rr][0], acc[rr][1], acc[rr][2], acc[rr][3]);
        *(float4*)&Mout[(size_t)row * Uu + tx * 4] = v;
    }
}

// ---------------------------------------------------------------------------
// rowupdate: fully fused per-row GRU-style gate update.
//   a = M0@W0 + M1@W1 + b_msg
//   z = sig(a@Wg0 + h@Ug0 + bg0); r = sig(a@Wg1 + h@Ug1 + bg1)
//   c = tanh(a@Wg2 + (r*h)@Ug2 + bg2); h = (1-z)h + z c
// grid(8, B): 16 rows per block, 256 threads. Thread owns (row, 4 cols).
// ---------------------------------------------------------------------------
__global__ void rowupdate_kernel(const float* __restrict__ W_msg,
                                 const float* __restrict__ b_msg,
                                 const float* __restrict__ Wg,
                                 const float* __restrict__ Ug,
                                 const float* __restrict__ bg,
                                 int l) {
    int tile = blockIdx.x;   // 0..7
    int b    = blockIdx.y;

    __shared__ float sh[16][64];
    __shared__ float sM0[16][64];   // reused as rh buffer after 'a' phase
    __shared__ float sM1[16][64];
    __shared__ float sa[16][64];
    __shared__ float sW[64][64];

    int tid = threadIdx.x;
    int row = tid >> 4;      // 0..15
    int cg  = tid & 15;
    int col = cg * 4;
    int r0  = tile * 16;

    const float* hb = g_h + ((size_t)b * Nn + r0) * Uu;
    const float* M0 = g_M + (((size_t)b * Ee + 0) * Nn + r0) * Uu;
    const float* M1 = g_M + (((size_t)b * Ee + 1) * Nn + r0) * Uu;

    {
        int i = tid * 4;  // covers 0..1020, exactly all 1024 floats
        *(float4*)&sh[0][i]  = *(const float4*)&hb[i];
        *(float4*)&sM0[0][i] = *(const float4*)&M0[i];
        *(float4*)&sM1[0][i] = *(const float4*)&M1[i];
    }

    // stage one 64x64 weight matrix into sW (syncs protect prior readers
    // of sW and make freshly written tiles visible)
    auto loadW = [&](const float* src) {
        __syncthreads();
        for (int i = tid * 4; i < 4096; i += 1024)
            *(float4*)&sW[0][i] = *(const float4*)&src[i];
        __syncthreads();
    };

    auto gemm = [&](float* accv, const float (*X)[64]) {
        #pragma unroll 4
        for (int k = 0; k < 64; k++) {
            float x = X[row][k];
            float4 w = *(const float4*)&sW[k][col];
            accv[0] += x * w.x; accv[1] += x * w.y;
            accv[2] += x * w.z; accv[3] += x * w.w;
        }
    };

    // --- a = M0@W0 + M1@W1 + b_msg ---
    float acc[4] = {0.f, 0.f, 0.f, 0.f};
    loadW(W_msg + ((size_t)l * Ee + 0) * Uu * Uu);
    float4 h4 = *(const float4*)&sh[row][col];   // tiles visible after loadW sync
    gemm(acc, sM0);
    loadW(W_msg + ((size_t)l * Ee + 1) * Uu * Uu);
    gemm(acc, sM1);
    {
        float4 bm = *(const float4*)&b_msg[l * Uu + col];
        acc[0] += bm.x; acc[1] += bm.y; acc[2] += bm.z; acc[3] += bm.w;
        *(float4*)&sa[row][col] = make_float4(acc[0], acc[1], acc[2], acc[3]);
    }

    // --- z = sigmoid(a@Wg0 + h@Ug0 + bg0) ---
    float accz[4];
    {
        float4 bb = *(const float4*)&bg[((size_t)l * 3 + 0) * Uu + col];
        accz[0] = bb.x; accz[1] = bb.y; accz[2] = bb.z; accz[3] = bb.w;
    }
    loadW(Ug + ((size_t)l * 3 + 0) * Uu * Uu);   // sync also publishes sa
    gemm(accz, sh);
    loadW(Wg + ((size_t)l * 3 + 0) * Uu * Uu);
    gemm(accz, sa);
    float z[4];
    #pragma unroll
    for (int j = 0; j < 4; j++) z[j] = 1.0f / (1.0f + expf(-accz[j]));

    // --- r = sigmoid(a@Wg1 + h@Ug1 + bg1); rh = r*h (into sM0) ---
    float accr[4];
    {
        float4 bb = *(const float4*)&bg[((size_t)l * 3 + 1) * Uu + col];
        accr[0] = bb.x; accr[1] = bb.y; accr[2] = bb.z; accr[3] = bb.w;
    }
    loadW(Ug + ((size_t)l * 3 + 1) * Uu * Uu);
    gemm(accr, sh);
    loadW(Wg + ((size_t)l * 3 + 1) * Uu * Uu);
    gemm(accr, sa);
    {
        float r_[4];
        #pragma unroll
        for (int j = 0; j < 4; j++) r_[j] = 1.0f / (1.0f + expf(-accr[j]));
        float4 rh = make_float4(r_[0] * h4.x, r_[1] * h4.y, r_[2] * h4.z, r_[3] * h4.w);
        *(float4*)&sM0[row][col] = rh;
    }

    // --- c = tanh(a@Wg2 + rh@Ug2 + bg2) ---
    float accc[4];
    {
        float4 bb = *(const float4*)&bg[((size_t)l * 3 + 2) * Uu + col];
        accc[0] = bb.x; accc[1] = bb.y; accc[2] = bb.z; accc[3] = bb.w;
    }
    loadW(Ug + ((size_t)l * 3 + 2) * Uu * Uu);   // sync publishes rh in sM0
    gemm(accc, sM0);
    loadW(Wg + ((size_t)l * 3 + 2) * Uu * Uu);
    gemm(accc, sa);

    // --- h_new = (1-z)*h + z*c ---
    float hn[4];
    hn[0] = (1.0f - z[0]) * h4.x + z[0] * tanhf(accc[0]);
    hn[1] = (1.0f - z[1]) * h4.y + z[1] * tanhf(accc[1]);
    hn[2] = (1.0f - z[2]) * h4.z + z[2] * tanhf(accc[2]);
    hn[3] = (1.0f - z[3]) * h4.w + z[3] * tanhf(accc[3]);

    float* hout = g_h + ((size_t)b * Nn + r0 + row) * Uu + col;
    *(float4*)hout = make_float4(hn[0], hn[1], hn[2], hn[3]);
}

// ---------------------------------------------------------------------------
// final: logits[b,n,:] = relu(h[b,n,:]) @ fc_w + fc_b; out[b,:] = max over n
// grid(B), 128 threads (one per n).
// ---------------------------------------------------------------------------
__global__ void final_kernel(const float* __restrict__ fc_w,
                             const float* __restrict__ fc_b,
                             float* __restrict__ out) {
    int b = blockIdx.x;
    int n = threadIdx.x;   // 0..127

    __shared__ float sw[Uu * NC];
    __shared__ float slog[Nn][NC];

    for (int i = n; i < Uu * NC; i += 128) sw[i] = fc_w[i];
    __syncthreads();

    const float* hrow = g_h + ((size_t)b * Nn + n) * Uu;
    float acc[NC];
    #pragma unroll
    for (int c = 0; c < NC; c++) acc[c] = fc_b[c];
    for (int u = 0; u < Uu; u++) {
        float v = hrow[u];
        v = v > 0.f ? v : 0.f;
        #pragma unroll
        for (int c = 0; c < NC; c++) acc[c] += v * sw[u * NC + c];
    }
    #pragma unroll
    for (int c = 0; c < NC; c++) slog[n][c] = acc[c];
    __syncthreads();

    for (int s = 64; s > 0; s >>= 1) {
        if (n < s) {
            #pragma unroll
            for (int c = 0; c < NC; c++)
                slog[n][c] = fmaxf(slog[n][c], slog[n + s][c]);
        }
        __syncthreads();
    }
    if (n < NC) out[b * NC + n] = slog[0][n];
}

// ---------------------------------------------------------------------------
// Launch
// ---------------------------------------------------------------------------
extern "C" void kernel_launch(void* const* d_in, const int* in_sizes, int n_in,
                              void* d_out, int out_size) {
    const float* input_seq   = (const float*)d_in[0];  // (B,S,N*U)
    const int*   seq_lengths = (const int*)d_in[1];    // (B,)
    const float* Adj         = (const float*)d_in[2];  // (B,E,N,N)
    const float* W_msg       = (const float*)d_in[3];  // (L,E,U,U)
    const float* b_msg       = (const float*)d_in[4];  // (L,U)
    const float* Wg          = (const float*)d_in[5];  // (L,3,U,U)
    const float* Ug          = (const float*)d_in[6];  // (L,3,U,U)
    const float* bg          = (const float*)d_in[7];  // (L,3,U)
    const float* fc_w        = (const float*)d_in[8];  // (U,NC)
    const float* fc_b        = (const float*)d_in[9];  // (NC,)
    float* out = (float*)d_out;

    gather_kernel<<<Bb, 256>>>(input_seq, seq_lengths);

    for (int l = 0; l < Ll; l++) {
        for (int s = 0; s < NSTEP; s++) {
            msgmm_kernel<<<dim3(4, Ee, Bb), 256>>>(Adj);
            rowupdate_kernel<<<dim3(8, Bb), 256>>>(W_msg, b_msg, Wg, Ug, bg, l);
        }
    }

    final_kernel<<<Bb, 128>>>(fc_w, fc_b, out);
}